// round 5
// baseline (speedup 1.0000x reference)
#include <cuda_runtime.h>
#include <math.h>

// Problem constants
#define B  32
#define C  200
#define H  56
#define W  56
#define HW 3136
#define OH 224
#define OW 224
#define KS 33
#define PAD 16

#define MSP2 68         // 64x64 chunk pitch (floats); 272B rows, 16B aligned

// Scratch (device globals)
// g_delta layout: [hw][jj][b][e], jj = c/2, e = c&1 (6400 floats per pixel)
__device__ float g_delta[(size_t)HW * C * B];
__device__ float g_dist[(size_t)B * HW];
__device__ float g_up[(size_t)B * OH * OW];
__device__ float g_tmp[(size_t)B * OH * OW];
__device__ float g_gw[KS];

// ---------------- packed f32x2 helpers ----------------
__device__ __forceinline__ unsigned long long fma2(unsigned long long a,
                                                   unsigned long long b,
                                                   unsigned long long c)
{
    unsigned long long d;
    asm("fma.rn.f32x2 %0, %1, %2, %3;" : "=l"(d) : "l"(a), "l"(b), "l"(c));
    return d;
}
__device__ __forceinline__ float2 unpack2(unsigned long long v)
{
    float2 r;
    asm("mov.b64 {%0, %1}, %2;" : "=f"(r.x), "=f"(r.y) : "l"(v));
    return r;
}

// ---------------------------------------------------------------------------
// Kernel 1: delta prepass. emb[b][c][hw], mean[c][hw] -> g_delta[hw][jj][b][e]
// ---------------------------------------------------------------------------
__global__ void prep_delta_kernel(const float* __restrict__ emb,
                                  const float* __restrict__ mean)
{
    __shared__ float s[8][32][33];
    const int hw0 = blockIdx.x * 32;
    const int c0  = blockIdx.y * 8;
    const int lane = threadIdx.x & 31;
    const int wrp  = threadIdx.x >> 5;

    const int c = c0 + wrp;
    const float m = mean[(size_t)c * HW + hw0 + lane];
    #pragma unroll 4
    for (int b = 0; b < B; b++) {
        float e = emb[((size_t)b * C + c) * HW + hw0 + lane];
        s[wrp][b][lane] = e - m;
    }
    __syncthreads();

    const int b  = threadIdx.x & 31;
    const int cl = threadIdx.x >> 5;
    const int cc = c0 + cl;
    const int doff = (cc >> 1) * 64 + b * 2 + (cc & 1);
    #pragma unroll 4
    for (int hwl = 0; hwl < 32; hwl++) {
        g_delta[(size_t)(hw0 + hwl) * (C * B) + doff] = s[cl][b][hwl];
    }
}

// ---------------------------------------------------------------------------
// Kernel 2: per-pixel mahalanobis, symmetric-block schedule (R4) with
// j-packed f32x2 inner product (zero pack MOVs).
// CTA = 1 pixel, 256 thr = 8 tx (4 b) x 32 ty (rows ty, ty+32 of 64-block).
// ---------------------------------------------------------------------------
__global__ void __launch_bounds__(256)
mahal_kernel(const float* __restrict__ invcov)
{
    extern __shared__ float sm[];
    float* Ds2 = sm;                      // 6400 floats [jj][b][e]
    float* Mb0 = sm + C * B;              // 64*68
    float* Mb1 = Mb0 + 64 * MSP2;         // 64*68 (also border staging)

    const int p   = blockIdx.x;
    const int tid = threadIdx.x;
    const int tx  = tid & 7;
    const int ty  = tid >> 3;
    const int b0  = tx * 4;

    const float* Mp = invcov + (size_t)p * (C * C);

    // chunk schedule: (I,J,weight); 64-blocks, J <= I
    const int   CI[6] = {0, 1, 1, 2, 2, 2};
    const int   CJ[6] = {0, 0, 1, 0, 1, 2};
    const float CW[6] = {1.f, 2.f, 1.f, 2.f, 2.f, 1.f};

    // ---- issue chunk 0 LDGs first ----
    float4 st[4];
    #pragma unroll
    for (int o = 0; o < 4; o++) {
        int e4 = o * 256 + tid;            // 1024 float4 = 64 rows x 16
        int il = e4 >> 4;
        int jl = (e4 & 15) * 4;
        st[o] = *(const float4*)&Mp[(size_t)il * C + jl];
    }

    // ---- stage delta (coalesced, layout-agnostic copy) ----
    const float* dsrc = g_delta + (size_t)p * (C * B);
    for (int i = tid * 4; i < C * B; i += 1024)
        *(float4*)&Ds2[i] = *(const float4*)&dsrc[i];

    // ---- stage border rows 192..199 (8 x 200) into Mb1 ----
    for (int i = tid * 4; i < 8 * C; i += 1024)
        *(float4*)&Mb1[i] = *(const float4*)&Mp[(size_t)192 * C + i];

    __syncthreads();

    float q0 = 0.f, q1 = 0.f, q2 = 0.f, q3 = 0.f;

    // ---- border strip: rows 192..199, col-weight 2 (j<192) / 1 ----
    #pragma unroll
    for (int rr = 0; rr < 8; rr++) {
        const float* mrow = &Mb1[rr * C];
        float p0 = 0.f, p1 = 0.f, p2 = 0.f, p3 = 0.f;
        #pragma unroll
        for (int s = 0; s < 7; s++) {
            int j = ty + 32 * s;
            if (j < C) {
                float wm = mrow[j] * ((j < 192) ? 2.f : 1.f);
                int dbase = (j >> 1) * 64 + (j & 1) + b0 * 2;
                p0 += wm * Ds2[dbase + 0];
                p1 += wm * Ds2[dbase + 2];
                p2 += wm * Ds2[dbase + 4];
                p3 += wm * Ds2[dbase + 6];
            }
        }
        int i = 192 + rr;
        int ib = (i >> 1) * 64 + (i & 1) + b0 * 2;
        q0 += Ds2[ib + 0] * p0;
        q1 += Ds2[ib + 2] * p1;
        q2 += Ds2[ib + 4] * p2;
        q3 += Ds2[ib + 6] * p3;
    }

    // ---- 6-chunk pipeline over 64x64 blocks ----
    #pragma unroll
    for (int k = 0; k < 6; k++) {
        float* buf = (k & 1) ? Mb1 : Mb0;
        __syncthreads();                       // prior readers of buf done
        #pragma unroll
        for (int o = 0; o < 4; o++) {
            int e4 = o * 256 + tid;
            int il = e4 >> 4;
            int jl = (e4 & 15) * 4;
            *(float4*)&buf[il * MSP2 + jl] = st[o];
        }
        __syncthreads();

        if (k < 5) {                           // prefetch next chunk
            const float* src = Mp + (size_t)(64 * CI[k + 1]) * C + 64 * CJ[k + 1];
            #pragma unroll
            for (int o = 0; o < 4; o++) {
                int e4 = o * 256 + tid;
                int il = e4 >> 4;
                int jl = (e4 & 15) * 4;
                st[o] = *(const float4*)&src[(size_t)il * C + jl];
            }
        }

        // ---- compute chunk k: j-packed inner product ----
        unsigned long long a00 = 0ull, a01 = 0ull, a02 = 0ull, a03 = 0ull;
        unsigned long long a10 = 0ull, a11 = 0ull, a12 = 0ull, a13 = 0ull;
        const float* m0p = &buf[ty * MSP2];
        const float* m1p = &buf[(ty + 32) * MSP2];
        const float* dbase = &Ds2[(32 * CJ[k]) * 64 + b0 * 2];
        #pragma unroll
        for (int u = 0; u < 16; u++) {
            ulonglong2 m0 = *(const ulonglong2*)(m0p + u * 4);  // (m[4u],m[4u+1]),(m[4u+2],m[4u+3])
            ulonglong2 m1 = *(const ulonglong2*)(m1p + u * 4);
            const float* dp = dbase + (u * 2) * 64;
            ulonglong2 dA = *(const ulonglong2*)(dp);           // jj=2u, b0..b0+1
            ulonglong2 dB = *(const ulonglong2*)(dp + 4);       // jj=2u, b0+2..b0+3
            ulonglong2 dC = *(const ulonglong2*)(dp + 64);      // jj=2u+1
            ulonglong2 dD = *(const ulonglong2*)(dp + 68);

            a00 = fma2(m0.x, dA.x, a00);
            a01 = fma2(m0.x, dA.y, a01);
            a02 = fma2(m0.x, dB.x, a02);
            a03 = fma2(m0.x, dB.y, a03);
            a10 = fma2(m1.x, dA.x, a10);
            a11 = fma2(m1.x, dA.y, a11);
            a12 = fma2(m1.x, dB.x, a12);
            a13 = fma2(m1.x, dB.y, a13);

            a00 = fma2(m0.y, dC.x, a00);
            a01 = fma2(m0.y, dC.y, a01);
            a02 = fma2(m0.y, dD.x, a02);
            a03 = fma2(m0.y, dD.y, a03);
            a10 = fma2(m1.y, dC.x, a10);
            a11 = fma2(m1.y, dC.y, a11);
            a12 = fma2(m1.y, dD.x, a12);
            a13 = fma2(m1.y, dD.y, a13);
        }

        // ---- fold with weight: s_ib = even + odd ----
        {
            const float w = CW[k];
            const int i0 = 64 * CI[k] + ty;
            const int i1 = i0 + 32;
            const int ib0 = (i0 >> 1) * 64 + (i0 & 1) + b0 * 2;
            const int ib1 = (i1 >> 1) * 64 + (i1 & 1) + b0 * 2;
            float2 s00 = unpack2(a00), s01 = unpack2(a01);
            float2 s02 = unpack2(a02), s03 = unpack2(a03);
            float2 s10 = unpack2(a10), s11 = unpack2(a11);
            float2 s12 = unpack2(a12), s13 = unpack2(a13);
            q0 += w * (Ds2[ib0 + 0] * (s00.x + s00.y) + Ds2[ib1 + 0] * (s10.x + s10.y));
            q1 += w * (Ds2[ib0 + 2] * (s01.x + s01.y) + Ds2[ib1 + 2] * (s11.x + s11.y));
            q2 += w * (Ds2[ib0 + 4] * (s02.x + s02.y) + Ds2[ib1 + 4] * (s12.x + s12.y));
            q3 += w * (Ds2[ib0 + 6] * (s03.x + s03.y) + Ds2[ib1 + 6] * (s13.x + s13.y));
        }
    }

    // ---- block reduction over ty ----
    __syncthreads();
    float* red = Mb0;
    red[ty * 33 + b0 + 0] = q0;
    red[ty * 33 + b0 + 1] = q1;
    red[ty * 33 + b0 + 2] = q2;
    red[ty * 33 + b0 + 3] = q3;
    __syncthreads();
    if (tid < B) {
        float acc = 0.f;
        #pragma unroll
        for (int t = 0; t < 32; t++) acc += red[t * 33 + tid];
        g_dist[(size_t)tid * HW + p] = sqrtf(fmaxf(acc, 0.f));
    }
}

// ---------------------------------------------------------------------------
// Kernel 3: gaussian weight init
// ---------------------------------------------------------------------------
__global__ void gauss_init_kernel()
{
    if (threadIdx.x == 0 && blockIdx.x == 0) {
        float w[KS];
        float s = 0.f;
        for (int i = 0; i < KS; i++) {
            float x = (float)(i - (KS - 1) / 2);
            w[i] = expf(-(x * x) / (2.f * 16.f));
            s += w[i];
        }
        for (int i = 0; i < KS; i++) g_gw[i] = w[i] / s;
    }
}

// ---------------------------------------------------------------------------
// Kernel 4: bilinear upsample 56x56 -> 224x224
// ---------------------------------------------------------------------------
__global__ void upsample_kernel()
{
    int idx = blockIdx.x * 256 + threadIdx.x;
    const int total = B * OH * OW;
    if (idx >= total) return;
    int x = idx % OW;
    int y = (idx / OW) % OH;
    int b = idx / (OW * OH);

    float sy = y * 0.25f - 0.375f;
    float sx = x * 0.25f - 0.375f;
    float fy0 = floorf(sy), fx0 = floorf(sx);
    float ay = sy - fy0, ax = sx - fx0;
    int y0 = (int)fy0, x0 = (int)fx0;
    int y1 = min(y0 + 1, H - 1);
    int x1 = min(x0 + 1, W - 1);
    y0 = max(y0, 0);
    x0 = max(x0, 0);

    const float* src = g_dist + (size_t)b * HW;
    float v00 = src[y0 * W + x0];
    float v01 = src[y0 * W + x1];
    float v10 = src[y1 * W + x0];
    float v11 = src[y1 * W + x1];
    float top = v00 + ax * (v01 - v00);
    float bot = v10 + ax * (v11 - v10);
    g_up[idx] = top + ay * (bot - top);
}

// ---------------------------------------------------------------------------
// Kernels 5/6: separable gaussian blur, reflect padding
// ---------------------------------------------------------------------------
__device__ __forceinline__ int reflect224(int i)
{
    if (i < 0) i = -i;
    if (i > OW - 1) i = 2 * (OW - 1) - i;
    return i;
}

__global__ void blur_h_kernel()
{
    __shared__ float sgw[KS];
    if (threadIdx.x < KS) sgw[threadIdx.x] = g_gw[threadIdx.x];
    __syncthreads();

    int idx = blockIdx.x * 256 + threadIdx.x;
    const int total = B * OH * OW;
    if (idx >= total) return;
    int x = idx % OW;
    int row_base = idx - x;

    float acc = 0.f;
    #pragma unroll
    for (int t = 0; t < KS; t++) {
        int xs = reflect224(x + t - PAD);
        acc += sgw[t] * g_up[row_base + xs];
    }
    g_tmp[idx] = acc;
}

__global__ void blur_v_kernel(float* __restrict__ out)
{
    __shared__ float sgw[KS];
    if (threadIdx.x < KS) sgw[threadIdx.x] = g_gw[threadIdx.x];
    __syncthreads();

    int idx = blockIdx.x * 256 + threadIdx.x;
    const int total = B * OH * OW;
    if (idx >= total) return;
    int x = idx % OW;
    int y = (idx / OW) % OH;
    int b = idx / (OW * OH);
    const float* src = g_tmp + (size_t)b * OH * OW;

    float acc = 0.f;
    #pragma unroll
    for (int t = 0; t < KS; t++) {
        int ys = reflect224(y + t - PAD);
        acc += sgw[t] * src[ys * OW + x];
    }
    out[idx] = acc;
}

// ---------------------------------------------------------------------------
// Launch
// ---------------------------------------------------------------------------
extern "C" void kernel_launch(void* const* d_in, const int* in_sizes, int n_in,
                              void* d_out, int out_size)
{
    const float* emb    = (const float*)d_in[0];
    const float* mean   = (const float*)d_in[1];
    const float* invcov = (const float*)d_in[2];
    float* out = (float*)d_out;

    const int mahal_smem = (C * B + 2 * 64 * MSP2) * (int)sizeof(float);  // 60416
    cudaFuncSetAttribute(mahal_kernel,
                         cudaFuncAttributeMaxDynamicSharedMemorySize, mahal_smem);

    dim3 prep_grid(HW / 32, C / 8);
    prep_delta_kernel<<<prep_grid, 256>>>(emb, mean);

    mahal_kernel<<<HW, 256, mahal_smem>>>(invcov);

    gauss_init_kernel<<<1, 32>>>();

    const int total = B * OH * OW;
    const int nb = (total + 255) / 256;
    upsample_kernel<<<nb, 256>>>();
    blur_h_kernel<<<nb, 256>>>();
    blur_v_kernel<<<nb, 256>>>(out);
}

// round 6
// speedup vs baseline: 1.4656x; 1.4656x over previous
#include <cuda_runtime.h>
#include <math.h>

// Problem constants
#define B  32
#define C  200
#define H  56
#define W  56
#define HW 3136
#define OH 224
#define OW 224
#define KS 33
#define PAD 16

#define MSP2 68         // 64x64 M-chunk smem pitch (floats)
#define DPITCH 96       // delta smem pitch per jj: 8 tx-blocks x 12 floats

// Scratch (device globals)
// g_delta dense layout: [hw][jj][b*2+e], jj=c/2, e=c&1  (pitch 64 per jj)
__device__ float g_delta[(size_t)HW * C * B];
__device__ float g_dist[(size_t)B * HW];
__device__ float g_up[(size_t)B * OH * OW];
__device__ float g_tmp[(size_t)B * OH * OW];
__device__ float g_gw[KS];

// ---------------- packed f32x2 helpers ----------------
__device__ __forceinline__ unsigned long long fma2(unsigned long long a,
                                                   unsigned long long b,
                                                   unsigned long long c)
{
    unsigned long long d;
    asm("fma.rn.f32x2 %0, %1, %2, %3;" : "=l"(d) : "l"(a), "l"(b), "l"(c));
    return d;
}
__device__ __forceinline__ float2 unpack2(unsigned long long v)
{
    float2 r;
    asm("mov.b64 {%0, %1}, %2;" : "=f"(r.x), "=f"(r.y) : "l"(v));
    return r;
}

// ---------------------------------------------------------------------------
// Kernel 1: delta prepass. emb[b][c][hw], mean[c][hw] -> g_delta[hw][jj][b*2+e]
// Writes float2 (both e of a c-pair) fully coalesced.
// ---------------------------------------------------------------------------
__global__ void prep_delta_kernel(const float* __restrict__ emb,
                                  const float* __restrict__ mean)
{
    __shared__ float s[8][32][33];
    const int hw0 = blockIdx.x * 32;
    const int c0  = blockIdx.y * 8;        // multiple of 8 (even)
    const int lane = threadIdx.x & 31;
    const int wrp  = threadIdx.x >> 5;

    const int c = c0 + wrp;
    const float m = mean[(size_t)c * HW + hw0 + lane];
    #pragma unroll 4
    for (int b = 0; b < B; b++) {
        float e = emb[((size_t)b * C + c) * HW + hw0 + lane];
        s[wrp][b][lane] = e - m;
    }
    __syncthreads();

    // write phase: tid = cl2*64 + half*32 + b ; c-pair (2cl2, 2cl2+1)
    const int cl2  = threadIdx.x >> 6;          // 0..3
    const int b    = threadIdx.x & 31;
    const int half = (threadIdx.x >> 5) & 1;
    const int jj   = (c0 >> 1) + cl2;
    #pragma unroll 4
    for (int t = 0; t < 16; t++) {
        int hwl = half * 16 + t;
        float2 v = make_float2(s[2 * cl2][b][hwl], s[2 * cl2 + 1][b][hwl]);
        *(float2*)&g_delta[(size_t)(hw0 + hwl) * (C * B) + jj * 64 + b * 2] = v;
    }
}

// ---------------------------------------------------------------------------
// Kernel 2: per-pixel mahalanobis, symmetric 64x64 block schedule,
// j-packed f32x2 inner product with CONFLICT-FREE padded delta layout.
// smem delta idx(c, b): (c>>1)*96 + (b>>2)*12 + (b&3)*2 + (c&1)
// CTA = 1 pixel, 256 thr = 8 tx (4 b) x 32 ty (rows ty, ty+32 of 64-block).
// ---------------------------------------------------------------------------
__global__ void __launch_bounds__(256)
mahal_kernel(const float* __restrict__ invcov)
{
    extern __shared__ float sm[];
    float* Ds2 = sm;                      // 100 jj * 96 = 9600 floats
    float* Mb0 = Ds2 + 100 * DPITCH;      // 64*68
    float* Mb1 = Mb0 + 64 * MSP2;         // 64*68 (also border staging)

    const int p   = blockIdx.x;
    const int tid = threadIdx.x;
    const int tx  = tid & 7;
    const int ty  = tid >> 3;

    const float* Mp = invcov + (size_t)p * (C * C);

    // chunk schedule: (I,J,weight); 64-blocks, J <= I
    const int   CI[6] = {0, 1, 1, 2, 2, 2};
    const int   CJ[6] = {0, 0, 1, 0, 1, 2};
    const float CW[6] = {1.f, 2.f, 1.f, 2.f, 2.f, 1.f};

    // ---- issue chunk 0 LDGs first ----
    float4 st[4];
    #pragma unroll
    for (int o = 0; o < 4; o++) {
        int e4 = o * 256 + tid;            // 1024 float4 = 64 rows x 16
        int il = e4 >> 4;
        int jl = (e4 & 15) * 4;
        st[o] = *(const float4*)&Mp[(size_t)il * C + jl];
    }

    // ---- stage delta: dense gmem -> padded smem ----
    // dense idx i: jj = i>>6, r = i&63 (r%8 in {0,4} for float4)
    const float* dsrc = g_delta + (size_t)p * (C * B);
    for (int i4 = tid; i4 < 1600; i4 += 256) {
        float4 v = *(const float4*)&dsrc[i4 * 4];
        int i  = i4 * 4;
        int jj = i >> 6;
        int r  = i & 63;
        *(float4*)&Ds2[jj * DPITCH + (r >> 3) * 12 + (r & 7)] = v;
    }

    // ---- stage border rows 192..199 (8 x 200) into Mb1 ----
    for (int i = tid * 4; i < 8 * C; i += 1024)
        *(float4*)&Mb1[i] = *(const float4*)&Mp[(size_t)192 * C + i];

    __syncthreads();

    float q0 = 0.f, q1 = 0.f, q2 = 0.f, q3 = 0.f;

    // ---- border strip rows 192..199: col-weight 2 (j<192) / 1 (j>=192) ----
    #pragma unroll
    for (int rr = 0; rr < 8; rr++) {
        const float* mrow = &Mb1[rr * C];
        unsigned long long a2[4] = {0ull, 0ull, 0ull, 0ull};   // jj < 96 part
        unsigned long long a1[4] = {0ull, 0ull, 0ull, 0ull};   // jj >= 96 part
        #pragma unroll
        for (int s = 0; s < 3; s++) {
            int jj = ty + 32 * s;                               // < 96
            unsigned long long mm = *(const unsigned long long*)&mrow[jj * 2];
            const float* dp = &Ds2[jj * DPITCH + tx * 12];
            ulonglong2 dA = *(const ulonglong2*)(dp);           // b0,b1
            ulonglong2 dB = *(const ulonglong2*)(dp + 4);       // b2,b3
            a2[0] = fma2(mm, dA.x, a2[0]);
            a2[1] = fma2(mm, dA.y, a2[1]);
            a2[2] = fma2(mm, dB.x, a2[2]);
            a2[3] = fma2(mm, dB.y, a2[3]);
        }
        if (ty < 4) {
            int jj = 96 + ty;
            unsigned long long mm = *(const unsigned long long*)&mrow[jj * 2];
            const float* dp = &Ds2[jj * DPITCH + tx * 12];
            ulonglong2 dA = *(const ulonglong2*)(dp);
            ulonglong2 dB = *(const ulonglong2*)(dp + 4);
            a1[0] = fma2(mm, dA.x, a1[0]);
            a1[1] = fma2(mm, dA.y, a1[1]);
            a1[2] = fma2(mm, dB.x, a1[2]);
            a1[3] = fma2(mm, dB.y, a1[3]);
        }
        const int i = 192 + rr;
        const int dib = (i >> 1) * DPITCH + tx * 12 + (i & 1);
        float psum[4];
        #pragma unroll
        for (int bl = 0; bl < 4; bl++) {
            float2 s2 = unpack2(a2[bl]);
            float2 s1 = unpack2(a1[bl]);
            psum[bl] = 2.f * (s2.x + s2.y) + (s1.x + s1.y);
        }
        q0 += Ds2[dib + 0] * psum[0];
        q1 += Ds2[dib + 2] * psum[1];
        q2 += Ds2[dib + 4] * psum[2];
        q3 += Ds2[dib + 6] * psum[3];
    }

    // ---- 6-chunk pipeline over 64x64 blocks ----
    #pragma unroll
    for (int k = 0; k < 6; k++) {
        float* buf = (k & 1) ? Mb1 : Mb0;
        __syncthreads();                       // prior readers of buf done
        #pragma unroll
        for (int o = 0; o < 4; o++) {
            int e4 = o * 256 + tid;
            int il = e4 >> 4;
            int jl = (e4 & 15) * 4;
            *(float4*)&buf[il * MSP2 + jl] = st[o];
        }
        __syncthreads();

        if (k < 5) {                           // prefetch next chunk
            const float* src = Mp + (size_t)(64 * CI[k + 1]) * C + 64 * CJ[k + 1];
            #pragma unroll
            for (int o = 0; o < 4; o++) {
                int e4 = o * 256 + tid;
                int il = e4 >> 4;
                int jl = (e4 & 15) * 4;
                st[o] = *(const float4*)&src[(size_t)il * C + jl];
            }
        }

        // ---- compute chunk k: j-packed, conflict-free ----
        unsigned long long a00 = 0ull, a01 = 0ull, a02 = 0ull, a03 = 0ull;
        unsigned long long a10 = 0ull, a11 = 0ull, a12 = 0ull, a13 = 0ull;
        const float* m0p = &buf[ty * MSP2];
        const float* m1p = &buf[(ty + 32) * MSP2];
        const float* dbase = &Ds2[(32 * CJ[k]) * DPITCH + tx * 12];
        #pragma unroll
        for (int u = 0; u < 16; u++) {
            // m pair: cols (4u,4u+1) in .x, (4u+2,4u+3) in .y  (rel. to chunk)
            ulonglong2 m0 = *(const ulonglong2*)(m0p + u * 4);
            ulonglong2 m1 = *(const ulonglong2*)(m1p + u * 4);
            const float* dp = dbase + u * (2 * DPITCH);         // jjA = 2u
            ulonglong2 dA  = *(const ulonglong2*)(dp);          // jjA: b0,b1
            ulonglong2 dA2 = *(const ulonglong2*)(dp + 4);      // jjA: b2,b3
            ulonglong2 dB  = *(const ulonglong2*)(dp + DPITCH);     // jjB
            ulonglong2 dB2 = *(const ulonglong2*)(dp + DPITCH + 4);

            a00 = fma2(m0.x, dA.x,  a00);
            a01 = fma2(m0.x, dA.y,  a01);
            a02 = fma2(m0.x, dA2.x, a02);
            a03 = fma2(m0.x, dA2.y, a03);
            a10 = fma2(m1.x, dA.x,  a10);
            a11 = fma2(m1.x, dA.y,  a11);
            a12 = fma2(m1.x, dA2.x, a12);
            a13 = fma2(m1.x, dA2.y, a13);

            a00 = fma2(m0.y, dB.x,  a00);
            a01 = fma2(m0.y, dB.y,  a01);
            a02 = fma2(m0.y, dB2.x, a02);
            a03 = fma2(m0.y, dB2.y, a03);
            a10 = fma2(m1.y, dB.x,  a10);
            a11 = fma2(m1.y, dB.y,  a11);
            a12 = fma2(m1.y, dB2.x, a12);
            a13 = fma2(m1.y, dB2.y, a13);
        }

        // ---- fold with weight: s_ib = even + odd ----
        {
            const float w = CW[k];
            const int i0 = 64 * CI[k] + ty;
            const int i1 = i0 + 32;
            const int ib0 = (i0 >> 1) * DPITCH + tx * 12 + (i0 & 1);
            const int ib1 = (i1 >> 1) * DPITCH + tx * 12 + (i1 & 1);
            float2 s00 = unpack2(a00), s01 = unpack2(a01);
            float2 s02 = unpack2(a02), s03 = unpack2(a03);
            float2 s10 = unpack2(a10), s11 = unpack2(a11);
            float2 s12 = unpack2(a12), s13 = unpack2(a13);
            q0 += w * (Ds2[ib0 + 0] * (s00.x + s00.y) + Ds2[ib1 + 0] * (s10.x + s10.y));
            q1 += w * (Ds2[ib0 + 2] * (s01.x + s01.y) + Ds2[ib1 + 2] * (s11.x + s11.y));
            q2 += w * (Ds2[ib0 + 4] * (s02.x + s02.y) + Ds2[ib1 + 4] * (s12.x + s12.y));
            q3 += w * (Ds2[ib0 + 6] * (s03.x + s03.y) + Ds2[ib1 + 6] * (s13.x + s13.y));
        }
    }

    // ---- block reduction over ty ----
    __syncthreads();
    float* red = Mb0;
    const int b0 = tx * 4;
    red[ty * 33 + b0 + 0] = q0;
    red[ty * 33 + b0 + 1] = q1;
    red[ty * 33 + b0 + 2] = q2;
    red[ty * 33 + b0 + 3] = q3;
    __syncthreads();
    if (tid < B) {
        float acc = 0.f;
        #pragma unroll
        for (int t = 0; t < 32; t++) acc += red[t * 33 + tid];
        g_dist[(size_t)tid * HW + p] = sqrtf(fmaxf(acc, 0.f));
    }
}

// ---------------------------------------------------------------------------
// Kernel 3: gaussian weight init
// ---------------------------------------------------------------------------
__global__ void gauss_init_kernel()
{
    if (threadIdx.x == 0 && blockIdx.x == 0) {
        float w[KS];
        float s = 0.f;
        for (int i = 0; i < KS; i++) {
            float x = (float)(i - (KS - 1) / 2);
            w[i] = expf(-(x * x) / (2.f * 16.f));
            s += w[i];
        }
        for (int i = 0; i < KS; i++) g_gw[i] = w[i] / s;
    }
}

// ---------------------------------------------------------------------------
// Kernel 4: bilinear upsample 56x56 -> 224x224
// ---------------------------------------------------------------------------
__global__ void upsample_kernel()
{
    int idx = blockIdx.x * 256 + threadIdx.x;
    const int total = B * OH * OW;
    if (idx >= total) return;
    int x = idx % OW;
    int y = (idx / OW) % OH;
    int b = idx / (OW * OH);

    float sy = y * 0.25f - 0.375f;
    float sx = x * 0.25f - 0.375f;
    float fy0 = floorf(sy), fx0 = floorf(sx);
    float ay = sy - fy0, ax = sx - fx0;
    int y0 = (int)fy0, x0 = (int)fx0;
    int y1 = min(y0 + 1, H - 1);
    int x1 = min(x0 + 1, W - 1);
    y0 = max(y0, 0);
    x0 = max(x0, 0);

    const float* src = g_dist + (size_t)b * HW;
    float v00 = src[y0 * W + x0];
    float v01 = src[y0 * W + x1];
    float v10 = src[y1 * W + x0];
    float v11 = src[y1 * W + x1];
    float top = v00 + ax * (v01 - v00);
    float bot = v10 + ax * (v11 - v10);
    g_up[idx] = top + ay * (bot - top);
}

// ---------------------------------------------------------------------------
// Kernels 5/6: separable gaussian blur, reflect padding
// ---------------------------------------------------------------------------
__device__ __forceinline__ int reflect224(int i)
{
    if (i < 0) i = -i;
    if (i > OW - 1) i = 2 * (OW - 1) - i;
    return i;
}

__global__ void blur_h_kernel()
{
    __shared__ float sgw[KS];
    if (threadIdx.x < KS) sgw[threadIdx.x] = g_gw[threadIdx.x];
    __syncthreads();

    int idx = blockIdx.x * 256 + threadIdx.x;
    const int total = B * OH * OW;
    if (idx >= total) return;
    int x = idx % OW;
    int row_base = idx - x;

    float acc = 0.f;
    #pragma unroll
    for (int t = 0; t < KS; t++) {
        int xs = reflect224(x + t - PAD);
        acc += sgw[t] * g_up[row_base + xs];
    }
    g_tmp[idx] = acc;
}

__global__ void blur_v_kernel(float* __restrict__ out)
{
    __shared__ float sgw[KS];
    if (threadIdx.x < KS) sgw[threadIdx.x] = g_gw[threadIdx.x];
    __syncthreads();

    int idx = blockIdx.x * 256 + threadIdx.x;
    const int total = B * OH * OW;
    if (idx >= total) return;
    int x = idx % OW;
    int y = (idx / OW) % OH;
    int b = idx / (OW * OH);
    const float* src = g_tmp + (size_t)b * OH * OW;

    float acc = 0.f;
    #pragma unroll
    for (int t = 0; t < KS; t++) {
        int ys = reflect224(y + t - PAD);
        acc += sgw[t] * src[ys * OW + x];
    }
    out[idx] = acc;
}

// ---------------------------------------------------------------------------
// Launch
// ---------------------------------------------------------------------------
extern "C" void kernel_launch(void* const* d_in, const int* in_sizes, int n_in,
                              void* d_out, int out_size)
{
    const float* emb    = (const float*)d_in[0];
    const float* mean   = (const float*)d_in[1];
    const float* invcov = (const float*)d_in[2];
    float* out = (float*)d_out;

    const int mahal_smem = (100 * DPITCH + 2 * 64 * MSP2) * (int)sizeof(float); // 73216
    cudaFuncSetAttribute(mahal_kernel,
                         cudaFuncAttributeMaxDynamicSharedMemorySize, mahal_smem);

    dim3 prep_grid(HW / 32, C / 8);
    prep_delta_kernel<<<prep_grid, 256>>>(emb, mean);

    mahal_kernel<<<HW, 256, mahal_smem>>>(invcov);

    gauss_init_kernel<<<1, 32>>>();

    const int total = B * OH * OW;
    const int nb = (total + 255) / 256;
    upsample_kernel<<<nb, 256>>>();
    blur_h_kernel<<<nb, 256>>>();
    blur_v_kernel<<<nb, 256>>>(out);
}

// round 7
// speedup vs baseline: 2.0176x; 1.3766x over previous
#include <cuda_runtime.h>
#include <math.h>

// Problem constants
#define B  32
#define C  200
#define H  56
#define W  56
#define HW 3136
#define OH 224
#define OW 224
#define KS 33
#define PAD 16

#define MSP2 68         // 64x64 chunk pitch (floats); 272B rows, 16B aligned

// Scratch (device globals) — g_delta layout: [hw][c][b]
__device__ float g_delta[(size_t)HW * C * B];
__device__ float g_dist[(size_t)B * HW];
__device__ float g_up[(size_t)B * OH * OW];
__device__ float g_tmp[(size_t)B * OH * OW];
__device__ float g_gw[KS];

// ---------------- packed f32x2 helpers ----------------
__device__ __forceinline__ unsigned long long fma2(unsigned long long a,
                                                   unsigned long long b,
                                                   unsigned long long c)
{
    unsigned long long d;
    asm("fma.rn.f32x2 %0, %1, %2, %3;" : "=l"(d) : "l"(a), "l"(b), "l"(c));
    return d;
}
__device__ __forceinline__ unsigned long long pack2(float x)
{
    unsigned long long d;
    asm("mov.b64 %0, {%1, %1};" : "=l"(d) : "f"(x));
    return d;
}
__device__ __forceinline__ float2 unpack2(unsigned long long v)
{
    float2 r;
    asm("mov.b64 {%0, %1}, %2;" : "=f"(r.x), "=f"(r.y) : "l"(v));
    return r;
}

// ---------------------------------------------------------------------------
// Kernel 1: delta transpose prepass: emb[b][c][hw] -> g_delta[hw][c][b]
// ---------------------------------------------------------------------------
__global__ void prep_delta_kernel(const float* __restrict__ emb,
                                  const float* __restrict__ mean)
{
    __shared__ float s[8][32][33];
    const int hw0 = blockIdx.x * 32;
    const int c0  = blockIdx.y * 8;
    const int lane = threadIdx.x & 31;
    const int wrp  = threadIdx.x >> 5;

    const int c = c0 + wrp;
    const float m = mean[(size_t)c * HW + hw0 + lane];
    #pragma unroll 4
    for (int b = 0; b < B; b++) {
        float e = emb[((size_t)b * C + c) * HW + hw0 + lane];
        s[wrp][b][lane] = e - m;
    }
    __syncthreads();

    const int b  = threadIdx.x & 31;
    const int cl = threadIdx.x >> 5;
    #pragma unroll 4
    for (int hwl = 0; hwl < 32; hwl++) {
        g_delta[(size_t)(hw0 + hwl) * (C * B) + (c0 + cl) * B + b] = s[cl][b][hwl];
    }
}

// ---------------------------------------------------------------------------
// Kernel 2: per-pixel mahalanobis, symmetric 64x64 schedule (proven R4),
// NEW geometry: 128 threads = 8 tx (4 b) x 16 ty; each thread computes
// 4 rows (ty, ty+16, ty+32, ty+48) x 4 batches -> 4 B/FFMA2 smem traffic.
// ---------------------------------------------------------------------------
__global__ void __launch_bounds__(128)
mahal_kernel(const float* __restrict__ invcov)
{
    extern __shared__ float sm[];
    float* Ds  = sm;                      // 6400 floats [j][b]
    float* Mb0 = sm + C * B;              // 64*68
    float* Mb1 = Mb0 + 64 * MSP2;         // 64*68 (also border staging)

    const int p   = blockIdx.x;
    const int tid = threadIdx.x;
    const int tx  = tid & 7;
    const int ty  = tid >> 3;             // 0..15
    const int b0  = tx * 4;

    const float* Mp = invcov + (size_t)p * (C * C);

    // chunk schedule: (I,J,weight); 64-blocks, J <= I
    const int   CI[6] = {0, 1, 1, 2, 2, 2};
    const int   CJ[6] = {0, 0, 1, 0, 1, 2};
    const float CW[6] = {1.f, 2.f, 1.f, 2.f, 2.f, 1.f};

    // ---- issue chunk 0 LDGs first (1024 float4 / 128 thr = 8 each) ----
    float4 st[8];
    #pragma unroll
    for (int o = 0; o < 8; o++) {
        int e4 = o * 128 + tid;
        int il = e4 >> 4;
        int jl = (e4 & 15) * 4;
        st[o] = *(const float4*)&Mp[(size_t)il * C + jl];
    }

    // ---- stage delta (coalesced) ----
    const float* dsrc = g_delta + (size_t)p * (C * B);
    #pragma unroll
    for (int i = tid * 4; i < C * B; i += 512)
        *(float4*)&Ds[i] = *(const float4*)&dsrc[i];

    // ---- stage border rows 192..199 (8 x 200) into Mb1 ----
    #pragma unroll
    for (int i = tid * 4; i < 8 * C; i += 512)
        *(float4*)&Mb1[i] = *(const float4*)&Mp[(size_t)192 * C + i];

    __syncthreads();

    float q0 = 0.f, q1 = 0.f, q2 = 0.f, q3 = 0.f;

    // ---- border strip: rows 192..199, col-weight 2 (j<192) / 1 ----
    #pragma unroll
    for (int rr = 0; rr < 8; rr++) {
        const float* mrow = &Mb1[rr * C];
        float p0 = 0.f, p1 = 0.f, p2 = 0.f, p3 = 0.f;
        #pragma unroll
        for (int s = 0; s < 12; s++) {            // j = ty + 16s < 192
            int j = ty + 16 * s;
            float wm = 2.f * mrow[j];
            float4 dj = *(const float4*)&Ds[j * B + b0];
            p0 += wm * dj.x; p1 += wm * dj.y;
            p2 += wm * dj.z; p3 += wm * dj.w;
        }
        if (ty < 8) {                              // j = 192 + ty, weight 1
            int j = 192 + ty;
            float wm = mrow[j];
            float4 dj = *(const float4*)&Ds[j * B + b0];
            p0 += wm * dj.x; p1 += wm * dj.y;
            p2 += wm * dj.z; p3 += wm * dj.w;
        }
        float4 di = *(const float4*)&Ds[(192 + rr) * B + b0];
        q0 += di.x * p0; q1 += di.y * p1; q2 += di.z * p2; q3 += di.w * p3;
    }

    // ---- 6-chunk pipeline over 64x64 blocks, register-staged double buffer ----
    #pragma unroll
    for (int k = 0; k < 6; k++) {
        float* buf = (k & 1) ? Mb1 : Mb0;
        __syncthreads();                       // prior readers of buf done
        #pragma unroll
        for (int o = 0; o < 8; o++) {
            int e4 = o * 128 + tid;
            int il = e4 >> 4;
            int jl = (e4 & 15) * 4;
            *(float4*)&buf[il * MSP2 + jl] = st[o];
        }
        __syncthreads();

        if (k < 5) {                           // prefetch next chunk
            const float* src = Mp + (size_t)(64 * CI[k + 1]) * C + 64 * CJ[k + 1];
            #pragma unroll
            for (int o = 0; o < 8; o++) {
                int e4 = o * 128 + tid;
                int il = e4 >> 4;
                int jl = (e4 & 15) * 4;
                st[o] = *(const float4*)&src[(size_t)il * C + jl];
            }
        }

        // compute chunk k: 4 rows x 4 batches per thread
        unsigned long long a00 = 0ull, a01 = 0ull;
        unsigned long long a10 = 0ull, a11 = 0ull;
        unsigned long long a20 = 0ull, a21 = 0ull;
        unsigned long long a30 = 0ull, a31 = 0ull;
        const float* m0p = &buf[(ty     ) * MSP2];
        const float* m1p = &buf[(ty + 16) * MSP2];
        const float* m2p = &buf[(ty + 32) * MSP2];
        const float* m3p = &buf[(ty + 48) * MSP2];
        const float* dbase = &Ds[(64 * CJ[k]) * B + b0];
        #pragma unroll
        for (int u = 0; u < 16; u++) {
            float4 mv0 = *(const float4*)(m0p + u * 4);
            float4 mv1 = *(const float4*)(m1p + u * 4);
            float4 mv2 = *(const float4*)(m2p + u * 4);
            float4 mv3 = *(const float4*)(m3p + u * 4);
            #pragma unroll
            for (int jj = 0; jj < 4; jj++) {
                ulonglong2 du = *(const ulonglong2*)(dbase + (u * 4 + jj) * B);
                float c0 = (jj == 0) ? mv0.x : (jj == 1) ? mv0.y : (jj == 2) ? mv0.z : mv0.w;
                float c1 = (jj == 0) ? mv1.x : (jj == 1) ? mv1.y : (jj == 2) ? mv1.z : mv1.w;
                float c2 = (jj == 0) ? mv2.x : (jj == 1) ? mv2.y : (jj == 2) ? mv2.z : mv2.w;
                float c3 = (jj == 0) ? mv3.x : (jj == 1) ? mv3.y : (jj == 2) ? mv3.z : mv3.w;
                unsigned long long m0 = pack2(c0);
                a00 = fma2(m0, du.x, a00);
                a01 = fma2(m0, du.y, a01);
                unsigned long long m1 = pack2(c1);
                a10 = fma2(m1, du.x, a10);
                a11 = fma2(m1, du.y, a11);
                unsigned long long m2 = pack2(c2);
                a20 = fma2(m2, du.x, a20);
                a21 = fma2(m2, du.y, a21);
                unsigned long long m3 = pack2(c3);
                a30 = fma2(m3, du.x, a30);
                a31 = fma2(m3, du.y, a31);
            }
        }

        // fold with weight
        {
            const float w = CW[k];
            const int ib = 64 * CI[k] + ty;
            float4 dv0 = *(const float4*)&Ds[(ib     ) * B + b0];
            float4 dv1 = *(const float4*)&Ds[(ib + 16) * B + b0];
            float4 dv2 = *(const float4*)&Ds[(ib + 32) * B + b0];
            float4 dv3 = *(const float4*)&Ds[(ib + 48) * B + b0];
            float2 s00 = unpack2(a00), s01 = unpack2(a01);
            float2 s10 = unpack2(a10), s11 = unpack2(a11);
            float2 s20 = unpack2(a20), s21 = unpack2(a21);
            float2 s30 = unpack2(a30), s31 = unpack2(a31);
            q0 += w * (dv0.x * s00.x + dv1.x * s10.x + dv2.x * s20.x + dv3.x * s30.x);
            q1 += w * (dv0.y * s00.y + dv1.y * s10.y + dv2.y * s20.y + dv3.y * s30.y);
            q2 += w * (dv0.z * s01.x + dv1.z * s11.x + dv2.z * s21.x + dv3.z * s31.x);
            q3 += w * (dv0.w * s01.y + dv1.w * s11.y + dv2.w * s21.y + dv3.w * s31.y);
        }
    }

    // ---- block reduction over ty (16 partials per b) ----
    __syncthreads();
    float* red = Mb0;                   // 16*33 floats scratch
    red[ty * 33 + b0 + 0] = q0;
    red[ty * 33 + b0 + 1] = q1;
    red[ty * 33 + b0 + 2] = q2;
    red[ty * 33 + b0 + 3] = q3;
    __syncthreads();
    if (tid < B) {
        float acc = 0.f;
        #pragma unroll
        for (int t = 0; t < 16; t++) acc += red[t * 33 + tid];
        g_dist[(size_t)tid * HW + p] = sqrtf(fmaxf(acc, 0.f));
    }
}

// ---------------------------------------------------------------------------
// Kernel 3: gaussian weight init
// ---------------------------------------------------------------------------
__global__ void gauss_init_kernel()
{
    if (threadIdx.x == 0 && blockIdx.x == 0) {
        float w[KS];
        float s = 0.f;
        for (int i = 0; i < KS; i++) {
            float x = (float)(i - (KS - 1) / 2);
            w[i] = expf(-(x * x) / (2.f * 16.f));
            s += w[i];
        }
        for (int i = 0; i < KS; i++) g_gw[i] = w[i] / s;
    }
}

// ---------------------------------------------------------------------------
// Kernel 4: bilinear upsample 56x56 -> 224x224
// ---------------------------------------------------------------------------
__global__ void upsample_kernel()
{
    int idx = blockIdx.x * 256 + threadIdx.x;
    const int total = B * OH * OW;
    if (idx >= total) return;
    int x = idx % OW;
    int y = (idx / OW) % OH;
    int b = idx / (OW * OH);

    float sy = y * 0.25f - 0.375f;
    float sx = x * 0.25f - 0.375f;
    float fy0 = floorf(sy), fx0 = floorf(sx);
    float ay = sy - fy0, ax = sx - fx0;
    int y0 = (int)fy0, x0 = (int)fx0;
    int y1 = min(y0 + 1, H - 1);
    int x1 = min(x0 + 1, W - 1);
    y0 = max(y0, 0);
    x0 = max(x0, 0);

    const float* src = g_dist + (size_t)b * HW;
    float v00 = src[y0 * W + x0];
    float v01 = src[y0 * W + x1];
    float v10 = src[y1 * W + x0];
    float v11 = src[y1 * W + x1];
    float top = v00 + ax * (v01 - v00);
    float bot = v10 + ax * (v11 - v10);
    g_up[idx] = top + ay * (bot - top);
}

// ---------------------------------------------------------------------------
// Kernels 5/6: separable gaussian blur, reflect padding
// ---------------------------------------------------------------------------
__device__ __forceinline__ int reflect224(int i)
{
    if (i < 0) i = -i;
    if (i > OW - 1) i = 2 * (OW - 1) - i;
    return i;
}

__global__ void blur_h_kernel()
{
    __shared__ float sgw[KS];
    if (threadIdx.x < KS) sgw[threadIdx.x] = g_gw[threadIdx.x];
    __syncthreads();

    int idx = blockIdx.x * 256 + threadIdx.x;
    const int total = B * OH * OW;
    if (idx >= total) return;
    int x = idx % OW;
    int row_base = idx - x;

    float acc = 0.f;
    #pragma unroll
    for (int t = 0; t < KS; t++) {
        int xs = reflect224(x + t - PAD);
        acc += sgw[t] * g_up[row_base + xs];
    }
    g_tmp[idx] = acc;
}

__global__ void blur_v_kernel(float* __restrict__ out)
{
    __shared__ float sgw[KS];
    if (threadIdx.x < KS) sgw[threadIdx.x] = g_gw[threadIdx.x];
    __syncthreads();

    int idx = blockIdx.x * 256 + threadIdx.x;
    const int total = B * OH * OW;
    if (idx >= total) return;
    int x = idx % OW;
    int y = (idx / OW) % OH;
    int b = idx / (OW * OH);
    const float* src = g_tmp + (size_t)b * OH * OW;

    float acc = 0.f;
    #pragma unroll
    for (int t = 0; t < KS; t++) {
        int ys = reflect224(y + t - PAD);
        acc += sgw[t] * src[ys * OW + x];
    }
    out[idx] = acc;
}

// ---------------------------------------------------------------------------
// Launch
// ---------------------------------------------------------------------------
extern "C" void kernel_launch(void* const* d_in, const int* in_sizes, int n_in,
                              void* d_out, int out_size)
{
    const float* emb    = (const float*)d_in[0];
    const float* mean   = (const float*)d_in[1];
    const float* invcov = (const float*)d_in[2];
    float* out = (float*)d_out;

    const int mahal_smem = (C * B + 2 * 64 * MSP2) * (int)sizeof(float);  // 60416
    cudaFuncSetAttribute(mahal_kernel,
                         cudaFuncAttributeMaxDynamicSharedMemorySize, mahal_smem);

    dim3 prep_grid(HW / 32, C / 8);
    prep_delta_kernel<<<prep_grid, 256>>>(emb, mean);

    mahal_kernel<<<HW, 128, mahal_smem>>>(invcov);

    gauss_init_kernel<<<1, 32>>>();

    const int total = B * OH * OW;
    const int nb = (total + 255) / 256;
    upsample_kernel<<<nb, 256>>>();
    blur_h_kernel<<<nb, 256>>>();
    blur_v_kernel<<<nb, 256>>>(out);
}

// round 8
// speedup vs baseline: 2.1201x; 1.0508x over previous
#include <cuda_runtime.h>
#include <math.h>

// Problem constants
#define B  32
#define C  200
#define H  56
#define W  56
#define HW 3136
#define OH 224
#define OW 224
#define KS 33
#define PAD 16

#define MSP2 68         // 64x64 chunk pitch (floats); 272B rows, 16B aligned

// Scratch (device globals) — g_delta layout: [hw][c][b]
__device__ float g_delta[(size_t)HW * C * B];
__device__ float g_dist[(size_t)B * HW];
__device__ float g_up[(size_t)B * OH * OW];
__device__ float g_tmp[(size_t)B * OH * OW];
__device__ float g_gw[KS];

// ---------------- packed f32x2 helpers ----------------
__device__ __forceinline__ unsigned long long fma2(unsigned long long a,
                                                   unsigned long long b,
                                                   unsigned long long c)
{
    unsigned long long d;
    asm("fma.rn.f32x2 %0, %1, %2, %3;" : "=l"(d) : "l"(a), "l"(b), "l"(c));
    return d;
}
__device__ __forceinline__ unsigned long long pack2(float x)
{
    unsigned long long d;
    asm("mov.b64 %0, {%1, %1};" : "=l"(d) : "f"(x));
    return d;
}
__device__ __forceinline__ float2 unpack2(unsigned long long v)
{
    float2 r;
    asm("mov.b64 {%0, %1}, %2;" : "=f"(r.x), "=f"(r.y) : "l"(v));
    return r;
}

// ---------------------------------------------------------------------------
// Kernel 1: delta transpose prepass: emb[b][c][hw] -> g_delta[hw][c][b]
// ---------------------------------------------------------------------------
__global__ void prep_delta_kernel(const float* __restrict__ emb,
                                  const float* __restrict__ mean)
{
    __shared__ float s[8][32][33];
    const int hw0 = blockIdx.x * 32;
    const int c0  = blockIdx.y * 8;
    const int lane = threadIdx.x & 31;
    const int wrp  = threadIdx.x >> 5;

    const int c = c0 + wrp;
    const float m = mean[(size_t)c * HW + hw0 + lane];
    #pragma unroll 4
    for (int b = 0; b < B; b++) {
        float e = emb[((size_t)b * C + c) * HW + hw0 + lane];
        s[wrp][b][lane] = e - m;
    }
    __syncthreads();

    const int b  = threadIdx.x & 31;
    const int cl = threadIdx.x >> 5;
    #pragma unroll 4
    for (int hwl = 0; hwl < 32; hwl++) {
        g_delta[(size_t)(hw0 + hwl) * (C * B) + (c0 + cl) * B + b] = s[cl][b][hwl];
    }
}

// ---------------------------------------------------------------------------
// Kernel 2: per-pixel mahalanobis, symmetric 64x64 schedule.
// Geometry: 128 thr = 2 jg x 8 ty x 8 tx. Each thread: 8 rows (ty+8k) x
// 4 batches over a 32-column j-subrange (jg). Partial row-sums fold
// independently per jg (q = sum_g w*d_i*s_i^g), summed in final reduction.
// ---------------------------------------------------------------------------
__global__ void __launch_bounds__(128)
mahal_kernel(const float* __restrict__ invcov)
{
    extern __shared__ float sm[];
    float* Ds  = sm;                      // 6400 floats [j][b]
    float* Mb0 = sm + C * B;              // 64*68
    float* Mb1 = Mb0 + 64 * MSP2;         // 64*68 (also border staging)

    const int p   = blockIdx.x;
    const int tid = threadIdx.x;
    const int tx  = tid & 7;
    const int g   = tid >> 3;             // 0..15 (group = jg*8 + ty)
    const int ty  = g & 7;                // 0..7
    const int jg  = g >> 3;               // 0..1
    const int b0  = tx * 4;

    const float* Mp = invcov + (size_t)p * (C * C);

    // chunk schedule: (I,J,weight); 64-blocks, J <= I
    const int   CI[6] = {0, 1, 1, 2, 2, 2};
    const int   CJ[6] = {0, 0, 1, 0, 1, 2};
    const float CW[6] = {1.f, 2.f, 1.f, 2.f, 2.f, 1.f};

    // ---- issue chunk 0 LDGs first (1024 float4 / 128 thr = 8 each) ----
    float4 st[8];
    #pragma unroll
    for (int o = 0; o < 8; o++) {
        int e4 = o * 128 + tid;
        int il = e4 >> 4;
        int jl = (e4 & 15) * 4;
        st[o] = *(const float4*)&Mp[(size_t)il * C + jl];
    }

    // ---- stage delta (coalesced) ----
    const float* dsrc = g_delta + (size_t)p * (C * B);
    #pragma unroll
    for (int i = tid * 4; i < C * B; i += 512)
        *(float4*)&Ds[i] = *(const float4*)&dsrc[i];

    // ---- stage border rows 192..199 (8 x 200) into Mb1 ----
    #pragma unroll
    for (int i = tid * 4; i < 8 * C; i += 512)
        *(float4*)&Mb1[i] = *(const float4*)&Mp[(size_t)192 * C + i];

    __syncthreads();

    float q0 = 0.f, q1 = 0.f, q2 = 0.f, q3 = 0.f;

    // ---- border strip: rows 192..199, col-weight 2 (j<192) / 1 ----
    #pragma unroll
    for (int rr = 0; rr < 8; rr++) {
        const float* mrow = &Mb1[rr * C];
        float p0 = 0.f, p1 = 0.f, p2 = 0.f, p3 = 0.f;
        #pragma unroll
        for (int s = 0; s < 12; s++) {            // j = g + 16s < 192
            int j = g + 16 * s;
            float wm = 2.f * mrow[j];
            float4 dj = *(const float4*)&Ds[j * B + b0];
            p0 += wm * dj.x; p1 += wm * dj.y;
            p2 += wm * dj.z; p3 += wm * dj.w;
        }
        if (g < 8) {                               // j = 192 + g, weight 1
            int j = 192 + g;
            float wm = mrow[j];
            float4 dj = *(const float4*)&Ds[j * B + b0];
            p0 += wm * dj.x; p1 += wm * dj.y;
            p2 += wm * dj.z; p3 += wm * dj.w;
        }
        float4 di = *(const float4*)&Ds[(192 + rr) * B + b0];
        q0 += di.x * p0; q1 += di.y * p1; q2 += di.z * p2; q3 += di.w * p3;
    }

    // ---- 6-chunk pipeline over 64x64 blocks, register-staged double buffer ----
    #pragma unroll
    for (int k = 0; k < 6; k++) {
        float* buf = (k & 1) ? Mb1 : Mb0;
        __syncthreads();                       // prior readers of buf done
        #pragma unroll
        for (int o = 0; o < 8; o++) {
            int e4 = o * 128 + tid;
            int il = e4 >> 4;
            int jl = (e4 & 15) * 4;
            *(float4*)&buf[il * MSP2 + jl] = st[o];
        }
        __syncthreads();

        if (k < 5) {                           // prefetch next chunk
            const float* src = Mp + (size_t)(64 * CI[k + 1]) * C + 64 * CJ[k + 1];
            #pragma unroll
            for (int o = 0; o < 8; o++) {
                int e4 = o * 128 + tid;
                int il = e4 >> 4;
                int jl = (e4 & 15) * 4;
                st[o] = *(const float4*)&src[(size_t)il * C + jl];
            }
        }

        // ---- compute chunk k: 8 rows x 4 batches over 32-col subrange ----
        unsigned long long acc[8][2];
        #pragma unroll
        for (int r = 0; r < 8; r++) { acc[r][0] = 0ull; acc[r][1] = 0ull; }

        const float* dbase = &Ds[(64 * CJ[k] + jg * 32) * B + b0];
        const int mcol = jg * 32;
        #pragma unroll
        for (int u = 0; u < 8; u++) {
            float4 mv[8];
            #pragma unroll
            for (int r = 0; r < 8; r++)
                mv[r] = *(const float4*)&buf[(ty + 8 * r) * MSP2 + mcol + u * 4];
            #pragma unroll
            for (int jj = 0; jj < 4; jj++) {
                ulonglong2 du = *(const ulonglong2*)(dbase + (u * 4 + jj) * B);
                #pragma unroll
                for (int r = 0; r < 8; r++) {
                    float c = (jj == 0) ? mv[r].x : (jj == 1) ? mv[r].y
                            : (jj == 2) ? mv[r].z : mv[r].w;
                    unsigned long long m = pack2(c);
                    acc[r][0] = fma2(m, du.x, acc[r][0]);
                    acc[r][1] = fma2(m, du.y, acc[r][1]);
                }
            }
        }

        // ---- fold with weight (partial over this jg's columns) ----
        {
            const float w = CW[k];
            #pragma unroll
            for (int r = 0; r < 8; r++) {
                int i = 64 * CI[k] + ty + 8 * r;
                float4 dv = *(const float4*)&Ds[i * B + b0];
                float2 s0 = unpack2(acc[r][0]);
                float2 s1 = unpack2(acc[r][1]);
                q0 += w * dv.x * s0.x;
                q1 += w * dv.y * s0.y;
                q2 += w * dv.z * s1.x;
                q3 += w * dv.w * s1.y;
            }
        }
    }

    // ---- block reduction over 16 groups per b ----
    __syncthreads();
    float* red = Mb0;                   // 16*33 floats scratch
    red[g * 33 + b0 + 0] = q0;
    red[g * 33 + b0 + 1] = q1;
    red[g * 33 + b0 + 2] = q2;
    red[g * 33 + b0 + 3] = q3;
    __syncthreads();
    if (tid < B) {
        float acc = 0.f;
        #pragma unroll
        for (int t = 0; t < 16; t++) acc += red[t * 33 + tid];
        g_dist[(size_t)tid * HW + p] = sqrtf(fmaxf(acc, 0.f));
    }
}

// ---------------------------------------------------------------------------
// Kernel 3: gaussian weight init
// ---------------------------------------------------------------------------
__global__ void gauss_init_kernel()
{
    if (threadIdx.x == 0 && blockIdx.x == 0) {
        float w[KS];
        float s = 0.f;
        for (int i = 0; i < KS; i++) {
            float x = (float)(i - (KS - 1) / 2);
            w[i] = expf(-(x * x) / (2.f * 16.f));
            s += w[i];
        }
        for (int i = 0; i < KS; i++) g_gw[i] = w[i] / s;
    }
}

// ---------------------------------------------------------------------------
// Kernel 4: bilinear upsample 56x56 -> 224x224
// ---------------------------------------------------------------------------
__global__ void upsample_kernel()
{
    int idx = blockIdx.x * 256 + threadIdx.x;
    const int total = B * OH * OW;
    if (idx >= total) return;
    int x = idx % OW;
    int y = (idx / OW) % OH;
    int b = idx / (OW * OH);

    float sy = y * 0.25f - 0.375f;
    float sx = x * 0.25f - 0.375f;
    float fy0 = floorf(sy), fx0 = floorf(sx);
    float ay = sy - fy0, ax = sx - fx0;
    int y0 = (int)fy0, x0 = (int)fx0;
    int y1 = min(y0 + 1, H - 1);
    int x1 = min(x0 + 1, W - 1);
    y0 = max(y0, 0);
    x0 = max(x0, 0);

    const float* src = g_dist + (size_t)b * HW;
    float v00 = src[y0 * W + x0];
    float v01 = src[y0 * W + x1];
    float v10 = src[y1 * W + x0];
    float v11 = src[y1 * W + x1];
    float top = v00 + ax * (v01 - v00);
    float bot = v10 + ax * (v11 - v10);
    g_up[idx] = top + ay * (bot - top);
}

// ---------------------------------------------------------------------------
// Kernels 5/6: separable gaussian blur, reflect padding
// ---------------------------------------------------------------------------
__device__ __forceinline__ int reflect224(int i)
{
    if (i < 0) i = -i;
    if (i > OW - 1) i = 2 * (OW - 1) - i;
    return i;
}

__global__ void blur_h_kernel()
{
    __shared__ float sgw[KS];
    if (threadIdx.x < KS) sgw[threadIdx.x] = g_gw[threadIdx.x];
    __syncthreads();

    int idx = blockIdx.x * 256 + threadIdx.x;
    const int total = B * OH * OW;
    if (idx >= total) return;
    int x = idx % OW;
    int row_base = idx - x;

    float acc = 0.f;
    #pragma unroll
    for (int t = 0; t < KS; t++) {
        int xs = reflect224(x + t - PAD);
        acc += sgw[t] * g_up[row_base + xs];
    }
    g_tmp[idx] = acc;
}

__global__ void blur_v_kernel(float* __restrict__ out)
{
    __shared__ float sgw[KS];
    if (threadIdx.x < KS) sgw[threadIdx.x] = g_gw[threadIdx.x];
    __syncthreads();

    int idx = blockIdx.x * 256 + threadIdx.x;
    const int total = B * OH * OW;
    if (idx >= total) return;
    int x = idx % OW;
    int y = (idx / OW) % OH;
    int b = idx / (OW * OH);
    const float* src = g_tmp + (size_t)b * OH * OW;

    float acc = 0.f;
    #pragma unroll
    for (int t = 0; t < KS; t++) {
        int ys = reflect224(y + t - PAD);
        acc += sgw[t] * src[ys * OW + x];
    }
    out[idx] = acc;
}

// ---------------------------------------------------------------------------
// Launch
// ---------------------------------------------------------------------------
extern "C" void kernel_launch(void* const* d_in, const int* in_sizes, int n_in,
                              void* d_out, int out_size)
{
    const float* emb    = (const float*)d_in[0];
    const float* mean   = (const float*)d_in[1];
    const float* invcov = (const float*)d_in[2];
    float* out = (float*)d_out;

    const int mahal_smem = (C * B + 2 * 64 * MSP2) * (int)sizeof(float);  // 60416
    cudaFuncSetAttribute(mahal_kernel,
                         cudaFuncAttributeMaxDynamicSharedMemorySize, mahal_smem);

    dim3 prep_grid(HW / 32, C / 8);
    prep_delta_kernel<<<prep_grid, 256>>>(emb, mean);

    mahal_kernel<<<HW, 128, mahal_smem>>>(invcov);

    gauss_init_kernel<<<1, 32>>>();

    const int total = B * OH * OW;
    const int nb = (total + 255) / 256;
    upsample_kernel<<<nb, 256>>>();
    blur_h_kernel<<<nb, 256>>>();
    blur_v_kernel<<<nb, 256>>>(out);
}